// round 4
// baseline (speedup 1.0000x reference)
#include <cuda_runtime.h>

#define NN 100000
#define EE 1600000

// ---------------- scratch (static device globals; no runtime alloc) ----------------
__device__ float d_h1[NN * 128];            // layer1 linear output
__device__ float d_g1[NN * 128];            // ELU(aggregated layer1)
__device__ float d_h2[NN * 64];             // layer2 linear output
__device__ float d_z [NN * 64];             // final node embeddings
__device__ __align__(16) float d_as1[NN * 4];
__device__ __align__(16) float d_ad1[NN * 4];
__device__ float d_as2[NN];
__device__ float d_ad2[NN];
__device__ int   d_deg[NN];
__device__ int   d_offs[NN + 1];
__device__ int   d_cursor[NN];
__device__ int   d_srcs[EE];
__device__ int   d_is64;                    // 1 if edge arrays are int64, 0 if int32

__device__ __forceinline__ float lrelu(float x) { return x > 0.f ? x : 0.2f * x; }

// Read element i of an index array whose dtype (int32 vs int64) is in d_is64.
__device__ __forceinline__ int edge_at(const void* p, int i) {
    if (d_is64) return (int)((const long long*)p)[i];
    return ((const int*)p)[i];
}
__device__ __forceinline__ int clampi(int v, int n) {
    return v < 0 ? 0 : (v >= n ? n - 1 : v);
}

// ---------------- dtype probe ----------------
// int64 indices < 2^31 have zero high words at odd 32-bit positions.
__global__ void probe_k(const unsigned int* __restrict__ w) {
    d_is64 = (w[1] == 0u && w[3] == 0u && w[5] == 0u && w[7] == 0u) ? 1 : 0;
}

// ---------------- CSR build ----------------
__global__ void zero_deg_k(int n) {
    int i = blockIdx.x * blockDim.x + threadIdx.x;
    if (i < n) d_deg[i] = 0;
}

__global__ void count_k(const void* __restrict__ ei, int e) {
    int i = blockIdx.x * blockDim.x + threadIdx.x;
    if (i < e) atomicAdd(&d_deg[clampi(edge_at(ei, e + i), NN)], 1);
}

__global__ void scan_k(int n) {
    __shared__ int s[1024];
    __shared__ int carry;
    int tid = threadIdx.x;
    if (tid == 0) carry = 0;
    __syncthreads();
    for (int base = 0; base < n; base += 1024) {
        int i = base + tid;
        int v = (i < n) ? d_deg[i] : 0;
        s[tid] = v;
        __syncthreads();
        for (int off = 1; off < 1024; off <<= 1) {
            int t = (tid >= off) ? s[tid - off] : 0;
            __syncthreads();
            s[tid] += t;
            __syncthreads();
        }
        int excl = s[tid] - v;
        int c = carry;
        if (i < n) { d_offs[i] = c + excl; d_cursor[i] = c + excl; }
        __syncthreads();
        if (tid == 1023) carry = c + s[1023];
        __syncthreads();
    }
    if (tid == 0) d_offs[n] = carry;
}

__global__ void place_k(const void* __restrict__ ei, int e) {
    int i = blockIdx.x * blockDim.x + threadIdx.x;
    if (i < e) {
        int src = clampi(edge_at(ei, i), NN);
        int dv  = clampi(edge_at(ei, e + i), NN);
        int pos = atomicAdd(&d_cursor[dv], 1);
        if (pos < EE) d_srcs[pos] = src;
    }
}

// ---------------- GEMM1: h1 = emb @ W1 (128x128), fused alpha logits ----------------
__global__ __launch_bounds__(256) void gemm1_k(
    const float* __restrict__ A, const float* __restrict__ B,
    const float* __restrict__ a_s, const float* __restrict__ a_d, int n)
{
    __shared__ float As[64][32];
    __shared__ float Bs[32][128];
    int tid = threadIdx.x, tx = tid & 31, ty = tid >> 5;
    int row0 = blockIdx.x * 64;
    float acc[8][4];
#pragma unroll
    for (int r = 0; r < 8; r++)
#pragma unroll
        for (int c = 0; c < 4; c++) acc[r][c] = 0.f;

    for (int kc = 0; kc < 128; kc += 32) {
#pragma unroll
        for (int j = 0; j < 8; j++) {
            int lin = j * 256 + tid, r = lin >> 5, kk = lin & 31, row = row0 + r;
            As[r][kk] = (row < n) ? A[row * 128 + kc + kk] : 0.f;
        }
#pragma unroll
        for (int j = 0; j < 16; j++) {
            int lin = j * 256 + tid, kk = lin >> 7, col = lin & 127;
            Bs[kk][col] = B[(kc + kk) * 128 + col];
        }
        __syncthreads();
#pragma unroll
        for (int kk = 0; kk < 32; kk++) {
            float b0 = Bs[kk][tx], b1 = Bs[kk][tx + 32], b2 = Bs[kk][tx + 64], b3 = Bs[kk][tx + 96];
#pragma unroll
            for (int r = 0; r < 8; r++) {
                float a = As[ty * 8 + r][kk];
                acc[r][0] += a * b0; acc[r][1] += a * b1;
                acc[r][2] += a * b2; acc[r][3] += a * b3;
            }
        }
        __syncthreads();
    }

    float asr[4], adr[4];
#pragma unroll
    for (int c = 0; c < 4; c++) { asr[c] = a_s[c * 32 + tx]; adr[c] = a_d[c * 32 + tx]; }

#pragma unroll
    for (int r = 0; r < 8; r++) {
        int row = row0 + ty * 8 + r;
        bool ok = row < n;
        float vs[4], vd[4];
#pragma unroll
        for (int c = 0; c < 4; c++) {
            if (ok) d_h1[row * 128 + tx + 32 * c] = acc[r][c];
            vs[c] = acc[r][c] * asr[c];
            vd[c] = acc[r][c] * adr[c];
        }
#pragma unroll
        for (int off = 16; off; off >>= 1) {
#pragma unroll
            for (int c = 0; c < 4; c++) {
                vs[c] += __shfl_xor_sync(0xffffffffu, vs[c], off);
                vd[c] += __shfl_xor_sync(0xffffffffu, vd[c], off);
            }
        }
        if (ok && tx == 0) {
#pragma unroll
            for (int c = 0; c < 4; c++) { d_as1[row * 4 + c] = vs[c]; d_ad1[row * 4 + c] = vd[c]; }
        }
    }
}

// ---------------- gather layer 1: online softmax aggregation, 4 heads x 32 ch ----------------
__device__ __forceinline__ void upd(float& m, float& d, float& a, float e, float h) {
    if (e > m) { float sc = __expf(m - e); d = d * sc + 1.f; a = a * sc + h; m = e; }
    else       { float p = __expf(e - m); d += p; a += p * h; }
}

__global__ __launch_bounds__(256) void gather1_k(const float* __restrict__ b1, int n) {
    int w = (blockIdx.x * 256 + threadIdx.x) >> 5;
    int lane = threadIdx.x & 31;
    if (w >= n) return;
    float4 ad = *(const float4*)(d_ad1 + w * 4);
    float4 asv = *(const float4*)(d_as1 + w * 4);
    const float* hr = d_h1 + w * 128;
    // self-loop seeds the online softmax
    float m0 = lrelu(asv.x + ad.x), m1 = lrelu(asv.y + ad.y);
    float m2 = lrelu(asv.z + ad.z), m3 = lrelu(asv.w + ad.w);
    float dd0 = 1.f, dd1 = 1.f, dd2 = 1.f, dd3 = 1.f;
    float a0 = hr[lane], a1 = hr[lane + 32], a2 = hr[lane + 64], a3 = hr[lane + 96];

    int p = d_offs[w], pe = d_offs[w + 1];
    for (; p < pe; ++p) {
        int src = d_srcs[p];
        float4 as = *(const float4*)(d_as1 + src * 4);
        const float* hs = d_h1 + src * 128;
        float h0 = hs[lane], h1v = hs[lane + 32], h2v = hs[lane + 64], h3v = hs[lane + 96];
        upd(m0, dd0, a0, lrelu(as.x + ad.x), h0);
        upd(m1, dd1, a1, lrelu(as.y + ad.y), h1v);
        upd(m2, dd2, a2, lrelu(as.z + ad.z), h2v);
        upd(m3, dd3, a3, lrelu(as.w + ad.w), h3v);
    }
    float o;
    o = a0 / (dd0 + 1e-16f) + b1[lane];       d_g1[w * 128 + lane]      = o > 0.f ? o : expm1f(o);
    o = a1 / (dd1 + 1e-16f) + b1[lane + 32];  d_g1[w * 128 + lane + 32] = o > 0.f ? o : expm1f(o);
    o = a2 / (dd2 + 1e-16f) + b1[lane + 64];  d_g1[w * 128 + lane + 64] = o > 0.f ? o : expm1f(o);
    o = a3 / (dd3 + 1e-16f) + b1[lane + 96];  d_g1[w * 128 + lane + 96] = o > 0.f ? o : expm1f(o);
}

// ---------------- GEMM2: h2 = g1 @ W2 (128x64), fused alpha logits ----------------
__global__ __launch_bounds__(256) void gemm2_k(
    const float* __restrict__ B,
    const float* __restrict__ a_s, const float* __restrict__ a_d, int n)
{
    __shared__ float As[64][32];
    __shared__ float Bs[32][64];
    int tid = threadIdx.x, tx = tid & 31, ty = tid >> 5;
    int row0 = blockIdx.x * 64;
    float acc[8][2];
#pragma unroll
    for (int r = 0; r < 8; r++) { acc[r][0] = 0.f; acc[r][1] = 0.f; }

    for (int kc = 0; kc < 128; kc += 32) {
#pragma unroll
        for (int j = 0; j < 8; j++) {
            int lin = j * 256 + tid, r = lin >> 5, kk = lin & 31, row = row0 + r;
            As[r][kk] = (row < n) ? d_g1[row * 128 + kc + kk] : 0.f;
        }
#pragma unroll
        for (int j = 0; j < 8; j++) {
            int lin = j * 256 + tid, kk = lin >> 6, col = lin & 63;
            Bs[kk][col] = B[(kc + kk) * 64 + col];
        }
        __syncthreads();
#pragma unroll
        for (int kk = 0; kk < 32; kk++) {
            float b0 = Bs[kk][tx], b1 = Bs[kk][tx + 32];
#pragma unroll
            for (int r = 0; r < 8; r++) {
                float a = As[ty * 8 + r][kk];
                acc[r][0] += a * b0; acc[r][1] += a * b1;
            }
        }
        __syncthreads();
    }

    float as0 = a_s[tx], as1v = a_s[tx + 32];
    float ad0 = a_d[tx], ad1v = a_d[tx + 32];
#pragma unroll
    for (int r = 0; r < 8; r++) {
        int row = row0 + ty * 8 + r;
        bool ok = row < n;
        if (ok) { d_h2[row * 64 + tx] = acc[r][0]; d_h2[row * 64 + tx + 32] = acc[r][1]; }
        float vs = acc[r][0] * as0 + acc[r][1] * as1v;
        float vd = acc[r][0] * ad0 + acc[r][1] * ad1v;
#pragma unroll
        for (int off = 16; off; off >>= 1) {
            vs += __shfl_xor_sync(0xffffffffu, vs, off);
            vd += __shfl_xor_sync(0xffffffffu, vd, off);
        }
        if (ok && tx == 0) { d_as2[row] = vs; d_ad2[row] = vd; }
    }
}

// ---------------- gather layer 2: 1 head x 64 ch ----------------
__global__ __launch_bounds__(256) void gather2_k(const float* __restrict__ b2, int n) {
    int w = (blockIdx.x * 256 + threadIdx.x) >> 5;
    int lane = threadIdx.x & 31;
    if (w >= n) return;
    float ad = d_ad2[w];
    const float* hr = d_h2 + w * 64;
    float m = lrelu(d_as2[w] + ad);
    float dd = 1.f;
    float a0 = hr[lane], a1 = hr[lane + 32];
    int p = d_offs[w], pe = d_offs[w + 1];
    for (; p < pe; ++p) {
        int src = d_srcs[p];
        float ev = lrelu(d_as2[src] + ad);
        const float* hs = d_h2 + src * 64;
        float h0 = hs[lane], h1v = hs[lane + 32];
        if (ev > m) { float sc = __expf(m - ev); dd = dd * sc + 1.f; a0 = a0 * sc + h0; a1 = a1 * sc + h1v; m = ev; }
        else        { float pp = __expf(ev - m); dd += pp; a0 += pp * h0; a1 += pp * h1v; }
    }
    float inv = 1.f / (dd + 1e-16f);
    d_z[w * 64 + lane]      = a0 * inv + b2[lane];
    d_z[w * 64 + lane + 32] = a1 * inv + b2[lane + 32];
}

// ---------------- decode: dot(z[s], z[t]) over 64 dims ----------------
__global__ __launch_bounds__(256) void decode_k(const void* __restrict__ eli,
                                                float* __restrict__ out, int L) {
    int w = (blockIdx.x * 256 + threadIdx.x) >> 5;
    int lane = threadIdx.x & 31;
    if (w >= L) return;
    int s = clampi(edge_at(eli, w), NN);
    int t = clampi(edge_at(eli, L + w), NN);
    const float* zs = d_z + s * 64;
    const float* zt = d_z + t * 64;
    float sum = zs[lane] * zt[lane] + zs[lane + 32] * zt[lane + 32];
#pragma unroll
    for (int off = 16; off; off >>= 1) sum += __shfl_xor_sync(0xffffffffu, sum, off);
    if (lane == 0) out[w] = sum;
}

// ---------------- launch ----------------
extern "C" void kernel_launch(void* const* d_in, const int* in_sizes, int n_in,
                              void* d_out, int out_size) {
    const void* ei      = d_in[1];
    const void* eli     = d_in[2];
    const float* emb    = (const float*)d_in[3];
    const float* W1     = (const float*)d_in[4];
    const float* a_src1 = (const float*)d_in[5];
    const float* a_dst1 = (const float*)d_in[6];
    const float* b1     = (const float*)d_in[7];
    const float* W2     = (const float*)d_in[8];
    const float* a_src2 = (const float*)d_in[9];
    const float* a_dst2 = (const float*)d_in[10];
    const float* b2     = (const float*)d_in[11];

    int n = in_sizes[3] / 128;   // num nodes
    int e = in_sizes[1] / 2;     // num edges
    int L = in_sizes[2] / 2;     // num label edges
    float* out = (float*)d_out;

    // dtype probe + CSR build (self-loops handled implicitly in gather)
    probe_k<<<1, 1>>>((const unsigned int*)ei);
    zero_deg_k<<<(n + 255) / 256, 256>>>(n);
    count_k<<<(e + 255) / 256, 256>>>(ei, e);
    scan_k<<<1, 1024>>>(n);
    place_k<<<(e + 255) / 256, 256>>>(ei, e);

    // layer 1
    gemm1_k<<<(n + 63) / 64, 256>>>(emb, W1, a_src1, a_dst1, n);
    gather1_k<<<(n + 7) / 8, 256>>>(b1, n);

    // layer 2
    gemm2_k<<<(n + 63) / 64, 256>>>(W2, a_src2, a_dst2, n);
    gather2_k<<<(n + 7) / 8, 256>>>(b2, n);

    // decode
    decode_k<<<(L + 7) / 8, 256>>>(eli, out, L);
}

// round 5
// speedup vs baseline: 1.2766x; 1.2766x over previous
#include <cuda_runtime.h>

#define NN 100000
#define EE 1600000
#define SCAN_BLK 1024
#define MAX_NBLK 1024

// ---------------- scratch (static device globals; no runtime alloc) ----------------
__device__ float d_h1[NN * 128];            // layer1 linear output
__device__ float d_g1[NN * 128];            // ELU(aggregated layer1)
__device__ float d_h2[NN * 64];             // layer2 linear output
__device__ float d_z [NN * 64];             // final node embeddings
__device__ __align__(16) float d_as1[NN * 4];
__device__ __align__(16) float d_ad1[NN * 4];
__device__ float d_as2[NN];
__device__ float d_ad2[NN];
__device__ int   d_deg[NN];
__device__ int   d_offs[NN + 1];
__device__ int   d_cursor[NN];
__device__ int   d_srcs[EE];
__device__ int   d_bsums[MAX_NBLK];
__device__ int   d_total;
__device__ int   d_is64;                    // 1 if edge arrays are int64, 0 if int32

__device__ __forceinline__ float lrelu(float x) { return x > 0.f ? x : 0.2f * x; }

__device__ __forceinline__ int edge_at(const void* p, int i) {
    if (d_is64) return (int)((const long long*)p)[i];
    return ((const int*)p)[i];
}
__device__ __forceinline__ int clampi(int v, int n) {
    return v < 0 ? 0 : (v >= n ? n - 1 : v);
}

// ---------------- dtype probe ----------------
__global__ void probe_k(const unsigned int* __restrict__ w) {
    d_is64 = (w[1] == 0u && w[3] == 0u && w[5] == 0u && w[7] == 0u) ? 1 : 0;
}

// ---------------- CSR build ----------------
__global__ void zero_deg_k(int n) {
    int i = blockIdx.x * blockDim.x + threadIdx.x;
    if (i < n) d_deg[i] = 0;
}

__global__ void count_k(const void* __restrict__ ei, int e) {
    int i = blockIdx.x * blockDim.x + threadIdx.x;
    if (i < e) atomicAdd(&d_deg[clampi(edge_at(ei, e + i), NN)], 1);
}

// warp-shuffle inclusive scan helper
__device__ __forceinline__ int wscan(int x, int lane) {
#pragma unroll
    for (int off = 1; off < 32; off <<= 1) {
        int t = __shfl_up_sync(0xffffffffu, x, off);
        if (lane >= off) x += t;
    }
    return x;
}

// phase 1: per-block exclusive scan of d_deg -> d_offs (local), block total -> d_bsums
__global__ __launch_bounds__(SCAN_BLK) void scan1_k(int n) {
    __shared__ int wsum[32];
    int tid = threadIdx.x, lane = tid & 31, wid = tid >> 5;
    int i = blockIdx.x * SCAN_BLK + tid;
    int v = (i < n) ? d_deg[i] : 0;
    int x = wscan(v, lane);                    // inclusive within warp
    if (lane == 31) wsum[wid] = x;
    __syncthreads();
    if (wid == 0) wsum[lane] = wscan(wsum[lane], lane);  // inclusive scan of 32 warp sums
    __syncthreads();
    int base = (wid > 0) ? wsum[wid - 1] : 0;
    if (i < n) d_offs[i] = base + x - v;       // exclusive, block-local
    if (tid == SCAN_BLK - 1) d_bsums[blockIdx.x] = base + x;
}

// phase 2: single block exclusive scan of block sums (nb <= 1024)
__global__ __launch_bounds__(SCAN_BLK) void scan2_k(int nb) {
    __shared__ int wsum[32];
    int tid = threadIdx.x, lane = tid & 31, wid = tid >> 5;
    int v = (tid < nb) ? d_bsums[tid] : 0;
    int x = wscan(v, lane);
    if (lane == 31) wsum[wid] = x;
    __syncthreads();
    if (wid == 0) wsum[lane] = wscan(wsum[lane], lane);
    __syncthreads();
    int base = (wid > 0) ? wsum[wid - 1] : 0;
    int excl = base + x - v;
    if (tid < nb) d_bsums[tid] = excl;
    if (tid == nb - 1) d_total = excl + v;
}

// phase 3: add block offsets, fill cursor and sentinel
__global__ void scan3_k(int n) {
    int i = blockIdx.x * blockDim.x + threadIdx.x;
    if (i < n) {
        int v = d_offs[i] + d_bsums[i >> 10];
        d_offs[i] = v;
        d_cursor[i] = v;
    } else if (i == n) {
        d_offs[n] = d_total;
    }
}

__global__ void place_k(const void* __restrict__ ei, int e) {
    int i = blockIdx.x * blockDim.x + threadIdx.x;
    if (i < e) {
        int src = clampi(edge_at(ei, i), NN);
        int dv  = clampi(edge_at(ei, e + i), NN);
        int pos = atomicAdd(&d_cursor[dv], 1);
        if (pos < EE) d_srcs[pos] = src;
    }
}

// ---------------- GEMM1: h1 = emb @ W1 (128x128), fused alpha logits ----------------
__global__ __launch_bounds__(256) void gemm1_k(
    const float* __restrict__ A, const float* __restrict__ B,
    const float* __restrict__ a_s, const float* __restrict__ a_d, int n)
{
    __shared__ float As[64][32];
    __shared__ float Bs[32][128];
    int tid = threadIdx.x, tx = tid & 31, ty = tid >> 5;
    int row0 = blockIdx.x * 64;
    float acc[8][4];
#pragma unroll
    for (int r = 0; r < 8; r++)
#pragma unroll
        for (int c = 0; c < 4; c++) acc[r][c] = 0.f;

    for (int kc = 0; kc < 128; kc += 32) {
#pragma unroll
        for (int j = 0; j < 8; j++) {
            int lin = j * 256 + tid, r = lin >> 5, kk = lin & 31, row = row0 + r;
            As[r][kk] = (row < n) ? A[row * 128 + kc + kk] : 0.f;
        }
#pragma unroll
        for (int j = 0; j < 16; j++) {
            int lin = j * 256 + tid, kk = lin >> 7, col = lin & 127;
            Bs[kk][col] = B[(kc + kk) * 128 + col];
        }
        __syncthreads();
#pragma unroll
        for (int kk = 0; kk < 32; kk++) {
            float b0 = Bs[kk][tx], b1 = Bs[kk][tx + 32], b2 = Bs[kk][tx + 64], b3 = Bs[kk][tx + 96];
#pragma unroll
            for (int r = 0; r < 8; r++) {
                float a = As[ty * 8 + r][kk];
                acc[r][0] += a * b0; acc[r][1] += a * b1;
                acc[r][2] += a * b2; acc[r][3] += a * b3;
            }
        }
        __syncthreads();
    }

    float asr[4], adr[4];
#pragma unroll
    for (int c = 0; c < 4; c++) { asr[c] = a_s[c * 32 + tx]; adr[c] = a_d[c * 32 + tx]; }

#pragma unroll
    for (int r = 0; r < 8; r++) {
        int row = row0 + ty * 8 + r;
        bool ok = row < n;
        float vs[4], vd[4];
#pragma unroll
        for (int c = 0; c < 4; c++) {
            if (ok) d_h1[row * 128 + tx + 32 * c] = acc[r][c];
            vs[c] = acc[r][c] * asr[c];
            vd[c] = acc[r][c] * adr[c];
        }
#pragma unroll
        for (int off = 16; off; off >>= 1) {
#pragma unroll
            for (int c = 0; c < 4; c++) {
                vs[c] += __shfl_xor_sync(0xffffffffu, vs[c], off);
                vd[c] += __shfl_xor_sync(0xffffffffu, vd[c], off);
            }
        }
        if (ok && tx == 0) {
#pragma unroll
            for (int c = 0; c < 4; c++) { d_as1[row * 4 + c] = vs[c]; d_ad1[row * 4 + c] = vd[c]; }
        }
    }
}

// ---------------- gather layer 1: online softmax aggregation, 4 heads x 32 ch ----------------
__device__ __forceinline__ void upd(float& m, float& d, float& a, float e, float h) {
    if (e > m) { float sc = __expf(m - e); d = d * sc + 1.f; a = a * sc + h; m = e; }
    else       { float p = __expf(e - m); d += p; a += p * h; }
}

__global__ __launch_bounds__(256) void gather1_k(const float* __restrict__ b1, int n) {
    int w = (blockIdx.x * 256 + threadIdx.x) >> 5;
    int lane = threadIdx.x & 31;
    if (w >= n) return;
    float4 ad = *(const float4*)(d_ad1 + w * 4);
    float4 asv = *(const float4*)(d_as1 + w * 4);
    const float* hr = d_h1 + w * 128;
    // self-loop seeds the online softmax
    float m0 = lrelu(asv.x + ad.x), m1 = lrelu(asv.y + ad.y);
    float m2 = lrelu(asv.z + ad.z), m3 = lrelu(asv.w + ad.w);
    float dd0 = 1.f, dd1 = 1.f, dd2 = 1.f, dd3 = 1.f;
    float a0 = hr[lane], a1 = hr[lane + 32], a2 = hr[lane + 64], a3 = hr[lane + 96];

    int p = d_offs[w], pe = d_offs[w + 1];
    for (; p < pe; ++p) {
        int src = d_srcs[p];
        float4 as = *(const float4*)(d_as1 + src * 4);
        const float* hs = d_h1 + src * 128;
        float h0 = hs[lane], h1v = hs[lane + 32], h2v = hs[lane + 64], h3v = hs[lane + 96];
        upd(m0, dd0, a0, lrelu(as.x + ad.x), h0);
        upd(m1, dd1, a1, lrelu(as.y + ad.y), h1v);
        upd(m2, dd2, a2, lrelu(as.z + ad.z), h2v);
        upd(m3, dd3, a3, lrelu(as.w + ad.w), h3v);
    }
    float o;
    o = a0 / (dd0 + 1e-16f) + b1[lane];       d_g1[w * 128 + lane]      = o > 0.f ? o : expm1f(o);
    o = a1 / (dd1 + 1e-16f) + b1[lane + 32];  d_g1[w * 128 + lane + 32] = o > 0.f ? o : expm1f(o);
    o = a2 / (dd2 + 1e-16f) + b1[lane + 64];  d_g1[w * 128 + lane + 64] = o > 0.f ? o : expm1f(o);
    o = a3 / (dd3 + 1e-16f) + b1[lane + 96];  d_g1[w * 128 + lane + 96] = o > 0.f ? o : expm1f(o);
}

// ---------------- GEMM2: h2 = g1 @ W2 (128x64), fused alpha logits ----------------
__global__ __launch_bounds__(256) void gemm2_k(
    const float* __restrict__ B,
    const float* __restrict__ a_s, const float* __restrict__ a_d, int n)
{
    __shared__ float As[64][32];
    __shared__ float Bs[32][64];
    int tid = threadIdx.x, tx = tid & 31, ty = tid >> 5;
    int row0 = blockIdx.x * 64;
    float acc[8][2];
#pragma unroll
    for (int r = 0; r < 8; r++) { acc[r][0] = 0.f; acc[r][1] = 0.f; }

    for (int kc = 0; kc < 128; kc += 32) {
#pragma unroll
        for (int j = 0; j < 8; j++) {
            int lin = j * 256 + tid, r = lin >> 5, kk = lin & 31, row = row0 + r;
            As[r][kk] = (row < n) ? d_g1[row * 128 + kc + kk] : 0.f;
        }
#pragma unroll
        for (int j = 0; j < 8; j++) {
            int lin = j * 256 + tid, kk = lin >> 6, col = lin & 63;
            Bs[kk][col] = B[(kc + kk) * 64 + col];
        }
        __syncthreads();
#pragma unroll
        for (int kk = 0; kk < 32; kk++) {
            float b0 = Bs[kk][tx], b1 = Bs[kk][tx + 32];
#pragma unroll
            for (int r = 0; r < 8; r++) {
                float a = As[ty * 8 + r][kk];
                acc[r][0] += a * b0; acc[r][1] += a * b1;
            }
        }
        __syncthreads();
    }

    float as0 = a_s[tx], as1v = a_s[tx + 32];
    float ad0 = a_d[tx], ad1v = a_d[tx + 32];
#pragma unroll
    for (int r = 0; r < 8; r++) {
        int row = row0 + ty * 8 + r;
        bool ok = row < n;
        if (ok) { d_h2[row * 64 + tx] = acc[r][0]; d_h2[row * 64 + tx + 32] = acc[r][1]; }
        float vs = acc[r][0] * as0 + acc[r][1] * as1v;
        float vd = acc[r][0] * ad0 + acc[r][1] * ad1v;
#pragma unroll
        for (int off = 16; off; off >>= 1) {
            vs += __shfl_xor_sync(0xffffffffu, vs, off);
            vd += __shfl_xor_sync(0xffffffffu, vd, off);
        }
        if (ok && tx == 0) { d_as2[row] = vs; d_ad2[row] = vd; }
    }
}

// ---------------- gather layer 2: 1 head x 64 ch ----------------
__global__ __launch_bounds__(256) void gather2_k(const float* __restrict__ b2, int n) {
    int w = (blockIdx.x * 256 + threadIdx.x) >> 5;
    int lane = threadIdx.x & 31;
    if (w >= n) return;
    float ad = d_ad2[w];
    const float* hr = d_h2 + w * 64;
    float m = lrelu(d_as2[w] + ad);
    float dd = 1.f;
    float a0 = hr[lane], a1 = hr[lane + 32];
    int p = d_offs[w], pe = d_offs[w + 1];
    for (; p < pe; ++p) {
        int src = d_srcs[p];
        float ev = lrelu(d_as2[src] + ad);
        const float* hs = d_h2 + src * 64;
        float h0 = hs[lane], h1v = hs[lane + 32];
        if (ev > m) { float sc = __expf(m - ev); dd = dd * sc + 1.f; a0 = a0 * sc + h0; a1 = a1 * sc + h1v; m = ev; }
        else        { float pp = __expf(ev - m); dd += pp; a0 += pp * h0; a1 += pp * h1v; }
    }
    float inv = 1.f / (dd + 1e-16f);
    d_z[w * 64 + lane]      = a0 * inv + b2[lane];
    d_z[w * 64 + lane + 32] = a1 * inv + b2[lane + 32];
}

// ---------------- decode: dot(z[s], z[t]) over 64 dims ----------------
__global__ __launch_bounds__(256) void decode_k(const void* __restrict__ eli,
                                                float* __restrict__ out, int L) {
    int w = (blockIdx.x * 256 + threadIdx.x) >> 5;
    int lane = threadIdx.x & 31;
    if (w >= L) return;
    int s = clampi(edge_at(eli, w), NN);
    int t = clampi(edge_at(eli, L + w), NN);
    const float* zs = d_z + s * 64;
    const float* zt = d_z + t * 64;
    float sum = zs[lane] * zt[lane] + zs[lane + 32] * zt[lane + 32];
#pragma unroll
    for (int off = 16; off; off >>= 1) sum += __shfl_xor_sync(0xffffffffu, sum, off);
    if (lane == 0) out[w] = sum;
}

// ---------------- launch ----------------
extern "C" void kernel_launch(void* const* d_in, const int* in_sizes, int n_in,
                              void* d_out, int out_size) {
    const void* ei      = d_in[1];
    const void* eli     = d_in[2];
    const float* emb    = (const float*)d_in[3];
    const float* W1     = (const float*)d_in[4];
    const float* a_src1 = (const float*)d_in[5];
    const float* a_dst1 = (const float*)d_in[6];
    const float* b1     = (const float*)d_in[7];
    const float* W2     = (const float*)d_in[8];
    const float* a_src2 = (const float*)d_in[9];
    const float* a_dst2 = (const float*)d_in[10];
    const float* b2     = (const float*)d_in[11];

    int n = in_sizes[3] / 128;   // num nodes
    int e = in_sizes[1] / 2;     // num edges
    int L = in_sizes[2] / 2;     // num label edges
    float* out = (float*)d_out;
    int nblk = (n + SCAN_BLK - 1) / SCAN_BLK;

    // dtype probe + CSR build (self-loops handled implicitly in gather)
    probe_k<<<1, 1>>>((const unsigned int*)ei);
    zero_deg_k<<<(n + 255) / 256, 256>>>(n);
    count_k<<<(e + 255) / 256, 256>>>(ei, e);
    scan1_k<<<nblk, SCAN_BLK>>>(n);
    scan2_k<<<1, SCAN_BLK>>>(nblk);
    scan3_k<<<(n + 256) / 256, 256>>>(n);
    place_k<<<(e + 255) / 256, 256>>>(ei, e);

    // layer 1
    gemm1_k<<<(n + 63) / 64, 256>>>(emb, W1, a_src1, a_dst1, n);
    gather1_k<<<(n + 7) / 8, 256>>>(b1, n);

    // layer 2
    gemm2_k<<<(n + 63) / 64, 256>>>(W2, a_src2, a_dst2, n);
    gather2_k<<<(n + 7) / 8, 256>>>(b2, n);

    // decode
    decode_k<<<(L + 7) / 8, 256>>>(eli, out, L);
}